// round 7
// baseline (speedup 1.0000x reference)
#include <cuda_runtime.h>

#define N_NODES 100000
#define E_EDGES 1200000
#define DIM 64
#define EPS_BN 1e-5f
#define NB_N 391      // ceil(N_NODES/256)
#define NB_E 4688     // ceil(E_EDGES/256)
#define NWARPS_G 6250 // N_NODES/16
#define NB_G 782      // ceil(6250/8)

// ---------------- scratch (static device globals; no allocation) ----------------
__device__ int   g_cnt[N_NODES];
__device__ int   g_rowptr[N_NODES + 1];
__device__ int   g_cursor[N_NODES];
__device__ int   g_csr_src[E_EDGES];
__device__ int   g_part[NB_N];
__device__ float g_Y[(size_t)N_NODES * DIM];
__device__ float g_Z[(size_t)N_NODES * DIM];
__device__ float g_H[(size_t)N_NODES * DIM];
// packed B fragments: [pair][ (nt*8+ks)*128 + lane*4 + {hi0,hi1,lo0,lo1} ]
__device__ float g_Bpack[2][16 * 8 * 32 * 4];

// ---------------- tf32 helpers ----------------
__device__ __forceinline__ unsigned cvt_tf32(float x) {
    unsigned r;
    asm("cvt.rna.tf32.f32 %0, %1;" : "=r"(r) : "f"(x));
    return r;
}
__device__ __forceinline__ void mma_tf32(float* c, const unsigned* a, unsigned b0, unsigned b1) {
    asm("mma.sync.aligned.m16n8k8.row.col.f32.tf32.tf32.f32 "
        "{%0,%1,%2,%3}, {%4,%5,%6,%7}, {%8,%9}, {%0,%1,%2,%3};"
        : "+f"(c[0]), "+f"(c[1]), "+f"(c[2]), "+f"(c[3])
        : "r"(a[0]), "r"(a[1]), "r"(a[2]), "r"(a[3]), "r"(b0), "r"(b1));
}

// ---------------- prepack W fragments + zero g_cnt (one launch) ----------------
__global__ __launch_bounds__(256) void k_prepack_zero(const float* __restrict__ Wl1,
                                                      const float* __restrict__ Wr1,
                                                      const float* __restrict__ Wl2,
                                                      const float* __restrict__ Wr2) {
    int b = blockIdx.x;
    int t = threadIdx.x;
    if (b < 2) {
        int pair = b;
        const float* Wl = pair ? Wl2 : Wl1;
        const float* Wr = pair ? Wr2 : Wr1;
        for (int idx = t; idx < 4096; idx += 256) {   // 128 tiles * 32 lanes
            int tile = idx >> 5, lane = idx & 31;
            int nt = tile >> 3, ks = tile & 7;
            int n = nt * 8 + (lane >> 2);
            int k = ks * 8 + (lane & 3);
            const float* W = (n < 64) ? Wl : Wr;
            int nn = n & 63;
            float w0 = W[nn * 64 + k];
            float w1 = W[nn * 64 + k + 4];
            unsigned h0 = cvt_tf32(w0), h1 = cvt_tf32(w1);
            unsigned l0 = cvt_tf32(w0 - __uint_as_float(h0));
            unsigned l1 = cvt_tf32(w1 - __uint_as_float(h1));
            float4 v = make_float4(__uint_as_float(h0), __uint_as_float(h1),
                                   __uint_as_float(l0), __uint_as_float(l1));
            ((float4*)(g_Bpack[pair]))[idx] = v;
        }
    } else {
        int i = (b - 2) * 256 + t;
        if (i < N_NODES) g_cnt[i] = 0;
    }
}

// ---------------- tensor-core GEMM pair body: [Y|Z] = X @ [Wl|Wr]^T, 3xTF32 ----------------
__device__ __forceinline__ void gemm_tc_body(const float* __restrict__ X,
                                             const float* __restrict__ pack,
                                             float* __restrict__ Y,
                                             float* __restrict__ Z,
                                             int w, int lane) {
    int g = lane >> 2;          // row within tile
    int tg = lane & 3;          // thread in group
    int r0 = w * 16 + g;

    float c[16][4];
#pragma unroll
    for (int nt = 0; nt < 16; nt++) {
        c[nt][0] = 0.f; c[nt][1] = 0.f; c[nt][2] = 0.f; c[nt][3] = 0.f;
    }

    const float4* bp = (const float4*)pack;

#pragma unroll
    for (int ks = 0; ks < 8; ks++) {
        int k = ks * 8 + tg;
        float a00 = X[(size_t)r0 * 64 + k];
        float a10 = X[(size_t)(r0 + 8) * 64 + k];
        float a01 = X[(size_t)r0 * 64 + k + 4];
        float a11 = X[(size_t)(r0 + 8) * 64 + k + 4];

        unsigned ah[4], al[4];
        ah[0] = cvt_tf32(a00); al[0] = cvt_tf32(a00 - __uint_as_float(ah[0]));
        ah[1] = cvt_tf32(a10); al[1] = cvt_tf32(a10 - __uint_as_float(ah[1]));
        ah[2] = cvt_tf32(a01); al[2] = cvt_tf32(a01 - __uint_as_float(ah[2]));
        ah[3] = cvt_tf32(a11); al[3] = cvt_tf32(a11 - __uint_as_float(ah[3]));

#pragma unroll
        for (int nt = 0; nt < 16; nt++) {
            float4 b = bp[(nt * 8 + ks) * 32 + lane];
            unsigned bh0 = __float_as_uint(b.x), bh1 = __float_as_uint(b.y);
            unsigned bl0 = __float_as_uint(b.z), bl1 = __float_as_uint(b.w);
            mma_tf32(c[nt], ah, bh0, bh1);
            mma_tf32(c[nt], ah, bl0, bl1);
            mma_tf32(c[nt], al, bh0, bh1);
        }
    }

#pragma unroll
    for (int nt = 0; nt < 16; nt++) {
        int n0 = nt * 8 + 2 * tg;
        float* O = (nt < 8) ? Y : Z;
        int col = n0 & 63;
        ((float2*)(O + (size_t)r0 * 64 + col))[0] = make_float2(c[nt][0], c[nt][1]);
        ((float2*)(O + (size_t)(r0 + 8) * 64 + col))[0] = make_float2(c[nt][2], c[nt][3]);
    }
}

// ---------------- fused: [layer-1 TC GEMM pair | degree histogram] ----------------
__global__ __launch_bounds__(256) void k_fusedA(const float* __restrict__ X,
                                                const float* __restrict__ pack,
                                                const int* __restrict__ ei,
                                                float* __restrict__ Y,
                                                float* __restrict__ Z) {
    int b = blockIdx.x;
    if (b < NB_G) {
        int w = b * 8 + (threadIdx.x >> 5);
        if (w < NWARPS_G)
            gemm_tc_body(X, pack, Y, Z, w, threadIdx.x & 31);
    } else {
        int e = (b - NB_G) * 256 + threadIdx.x;
        if (e < E_EDGES) {
            int dst = ei[E_EDGES + e];
            if ((unsigned)dst < N_NODES) atomicAdd(&g_cnt[dst], 1);
        }
    }
}

// ---------------- plain TC gemm pair (layer 2) ----------------
__global__ __launch_bounds__(256) void k_gemm_tc(const float* __restrict__ X,
                                                 const float* __restrict__ pack,
                                                 float* __restrict__ Y,
                                                 float* __restrict__ Z) {
    int w = (blockIdx.x * 256 + threadIdx.x) >> 5;
    if (w >= NWARPS_G) return;
    gemm_tc_body(X, pack, Y, Z, w, threadIdx.x & 31);
}

// ---------------- CSR scan ----------------
__global__ __launch_bounds__(256) void k_blocksum() {
    __shared__ int sc[256];
    int t = threadIdx.x;
    int i = blockIdx.x * 256 + t;
    int v = (i < N_NODES) ? g_cnt[i] : 0;
    sc[t] = v;
    __syncthreads();
    for (int off = 128; off > 0; off >>= 1) {
        if (t < off) sc[t] += sc[t + off];
        __syncthreads();
    }
    if (t == 0) g_part[blockIdx.x] = sc[0];
}

__global__ __launch_bounds__(256) void k_scatter2() {
    __shared__ int sc[256];
    __shared__ int sbase[8];
    int t = threadIdx.x;
    int b = blockIdx.x;

    int acc = 0;
    for (int i = t; i < b; i += 256) acc += g_part[i];
#pragma unroll
    for (int o = 16; o > 0; o >>= 1) acc += __shfl_down_sync(0xffffffffu, acc, o);
    if ((t & 31) == 0) sbase[t >> 5] = acc;

    int i = b * 256 + t;
    int v = (i < N_NODES) ? g_cnt[i] : 0;
    sc[t] = v;
    __syncthreads();

    int base = 0;
#pragma unroll
    for (int w = 0; w < 8; w++) base += sbase[w];

    for (int off = 1; off < 256; off <<= 1) {
        int u = (t >= off) ? sc[t - off] : 0;
        __syncthreads();
        sc[t] += u;
        __syncthreads();
    }
    if (i < N_NODES) {
        int pos = base + sc[t] - v;
        g_rowptr[i] = pos;
        g_cursor[i] = pos;
    }
    if (b == NB_N - 1 && t == 255) g_rowptr[N_NODES] = base + sc[255];
}

__global__ void k_fill(const int* __restrict__ ei) {
    int e = blockIdx.x * blockDim.x + threadIdx.x;
    if (e < E_EDGES) {
        int src = ei[e];
        int dst = ei[E_EDGES + e];
        if ((unsigned)dst < N_NODES && (unsigned)src < N_NODES) {
            int pos = atomicAdd(&g_cursor[dst], 1);
            g_csr_src[pos] = src;
        }
    }
}

// ---------------- shared gather body: mean-aggregate Y into (ax, ay) ----------------
__device__ __forceinline__ void gather_body(const float* __restrict__ Y, int warp, int lane,
                                            float& ax, float& ay, float& inv) {
    int r0 = g_rowptr[warp];
    int r1 = g_rowptr[warp + 1];

    const float2* Y2 = (const float2*)Y;
    ax = 0.f; ay = 0.f;

    int e = r0;
    for (; e + 4 <= r1; e += 4) {
        int s0 = g_csr_src[e];
        int s1 = g_csr_src[e + 1];
        int s2 = g_csr_src[e + 2];
        int s3 = g_csr_src[e + 3];
        float2 v0 = Y2[(size_t)s0 * 32 + lane];
        float2 v1 = Y2[(size_t)s1 * 32 + lane];
        float2 v2 = Y2[(size_t)s2 * 32 + lane];
        float2 v3 = Y2[(size_t)s3 * 32 + lane];
        ax += (v0.x + v1.x) + (v2.x + v3.x);
        ay += (v0.y + v1.y) + (v2.y + v3.y);
    }
    if (e + 2 <= r1) {
        int s0 = g_csr_src[e];
        int s1 = g_csr_src[e + 1];
        float2 v0 = Y2[(size_t)s0 * 32 + lane];
        float2 v1 = Y2[(size_t)s1 * 32 + lane];
        ax += v0.x + v1.x;
        ay += v0.y + v1.y;
        e += 2;
    }
    if (e < r1) {
        float2 v = Y2[(size_t)g_csr_src[e] * 32 + lane];
        ax += v.x;
        ay += v.y;
    }
    int deg = r1 - r0;
    inv = 1.f / (float)(deg > 0 ? deg : 1);
}

// ---------------- layer-1 agg: H = relu(BN(mean + bl + Z)) ----------------
__global__ __launch_bounds__(256) void k_agg(const float* __restrict__ Y,
                                             const float* __restrict__ Z,
                                             const float* __restrict__ bl,
                                             const float* __restrict__ gam,
                                             const float* __restrict__ bet,
                                             const float* __restrict__ mu,
                                             const float* __restrict__ var,
                                             float* __restrict__ H) {
    int warp = (blockIdx.x * blockDim.x + threadIdx.x) >> 5;
    int lane = threadIdx.x & 31;
    if (warp >= N_NODES) return;

    float ax, ay, inv;
    gather_body(Y, warp, lane, ax, ay, inv);

    int j0 = 2 * lane, j1 = 2 * lane + 1;
    float2 z = ((const float2*)Z)[(size_t)warp * 32 + lane];
    float h0 = ax * inv + bl[j0] + z.x;
    float h1 = ay * inv + bl[j1] + z.y;
    float s0 = gam[j0] * rsqrtf(var[j0] + EPS_BN);
    float s1 = gam[j1] * rsqrtf(var[j1] + EPS_BN);
    h0 = fmaxf((h0 - mu[j0]) * s0 + bet[j0], 0.f);
    h1 = fmaxf((h1 - mu[j1]) * s1 + bet[j1], 0.f);
    ((float2*)H)[(size_t)warp * 32 + lane] = make_float2(h0, h1);
}

// ---------------- layer-2 agg + fused MLP head -> out ----------------
__global__ __launch_bounds__(512) void k_agg2_head(const float* __restrict__ Y,
                                                   const float* __restrict__ Z,
                                                   const float* __restrict__ bl,
                                                   const float* __restrict__ gam,
                                                   const float* __restrict__ bet,
                                                   const float* __restrict__ mu,
                                                   const float* __restrict__ var,
                                                   const float* __restrict__ mW1,
                                                   const float* __restrict__ mb1,
                                                   const float* __restrict__ mW2,
                                                   const float* __restrict__ mb2,
                                                   float* __restrict__ out) {
    __shared__ float2 sW1T[1024];   // sW1T[l*32+j] = (mW1[j][2l], mW1[j][2l+1])
    __shared__ float sb1[32];
    __shared__ float sw2[32];
    __shared__ float sb2;
    int tid = threadIdx.x;
    for (int i = tid; i < 1024; i += 512) {
        int l = i >> 5, j = i & 31;
        sW1T[i] = make_float2(mW1[j * 64 + 2 * l], mW1[j * 64 + 2 * l + 1]);
    }
    if (tid < 32) { sb1[tid] = mb1[tid]; sw2[tid] = mW2[tid]; }
    if (tid == 0) sb2 = mb2[0];
    __syncthreads();

    int warp = (blockIdx.x * 512 + tid) >> 5;
    int lane = tid & 31;
    if (warp >= N_NODES) return;

    float ax, ay, inv;
    gather_body(Y, warp, lane, ax, ay, inv);

    int j0 = 2 * lane, j1 = 2 * lane + 1;
    float2 z = ((const float2*)Z)[(size_t)warp * 32 + lane];
    float h0 = ax * inv + bl[j0] + z.x;
    float h1 = ay * inv + bl[j1] + z.y;
    float s0 = gam[j0] * rsqrtf(var[j0] + EPS_BN);
    float s1 = gam[j1] * rsqrtf(var[j1] + EPS_BN);
    h0 = fmaxf((h0 - mu[j0]) * s0 + bet[j0], 0.f);
    h1 = fmaxf((h1 - mu[j1]) * s1 + bet[j1], 0.f);

    // head: acc_j = sum_l h[2l..2l+1] . mW1[j][2l..2l+1]  (lane == j)
    float acc = 0.f;
#pragma unroll
    for (int l = 0; l < 32; l++) {
        float hx = __shfl_sync(0xffffffffu, h0, l);
        float hy = __shfl_sync(0xffffffffu, h1, l);
        float2 wv = sW1T[l * 32 + lane];
        acc = fmaf(hx, wv.x, acc);
        acc = fmaf(hy, wv.y, acc);
    }
    float r = fmaxf(acc + sb1[lane], 0.f) * sw2[lane];
#pragma unroll
    for (int o = 16; o > 0; o >>= 1)
        r += __shfl_xor_sync(0xffffffffu, r, o);
    if (lane == 0)
        out[warp] = 1.f / (1.f + __expf(-(r + sb2)));
}

// ---------------- launch ----------------
extern "C" void kernel_launch(void* const* d_in, const int* in_sizes, int n_in,
                              void* d_out, int out_size) {
    const float* x    = (const float*)d_in[0];
    const int*   ei   = (const int*)d_in[1];
    const float* Wl1  = (const float*)d_in[2];
    const float* bl1  = (const float*)d_in[3];
    const float* Wr1  = (const float*)d_in[4];
    const float* g1   = (const float*)d_in[5];
    const float* be1  = (const float*)d_in[6];
    const float* m1   = (const float*)d_in[7];
    const float* v1   = (const float*)d_in[8];
    const float* Wl2  = (const float*)d_in[9];
    const float* bl2  = (const float*)d_in[10];
    const float* Wr2  = (const float*)d_in[11];
    const float* g2   = (const float*)d_in[12];
    const float* be2  = (const float*)d_in[13];
    const float* m2   = (const float*)d_in[14];
    const float* v2   = (const float*)d_in[15];
    const float* mW1  = (const float*)d_in[16];
    const float* mb1  = (const float*)d_in[17];
    const float* mW2  = (const float*)d_in[18];
    const float* mb2  = (const float*)d_in[19];
    float* out = (float*)d_out;

    float* Y; cudaGetSymbolAddress((void**)&Y, g_Y);
    float* Z; cudaGetSymbolAddress((void**)&Z, g_Z);
    float* H; cudaGetSymbolAddress((void**)&H, g_H);
    float* Bp; cudaGetSymbolAddress((void**)&Bp, g_Bpack);

    // 1: prepack both W pairs + zero g_cnt
    k_prepack_zero<<<2 + NB_N, 256>>>(Wl1, Wr1, Wl2, Wr2);
    // 2: layer-1 TC GEMM pair overlapped with degree histogram
    k_fusedA<<<NB_G + NB_E, 256>>>(x, Bp, ei, Y, Z);
    // 3-5: CSR finalize
    k_blocksum<<<NB_N, 256>>>();
    k_scatter2<<<NB_N, 256>>>();
    k_fill<<<NB_E, 256>>>(ei);
    // 6: layer-1 aggregate
    k_agg<<<(N_NODES * 32 + 255) / 256, 256>>>(Y, Z, bl1, g1, be1, m1, v1, H);
    // 7: layer-2 TC GEMM pair
    k_gemm_tc<<<NB_G, 256>>>(H, Bp + 16384, Y, Z);
    // 8: layer-2 aggregate + fused MLP head
    k_agg2_head<<<(N_NODES * 32 + 511) / 512, 512>>>(Y, Z, bl2, g2, be2, m2, v2,
                                                     mW1, mb1, mW2, mb2, out);
}

// round 8
// speedup vs baseline: 1.3331x; 1.3331x over previous
#include <cuda_runtime.h>

#define N_NODES 100000
#define E_EDGES 1200000
#define DIM 64
#define EPS_BN 1e-5f
#define NB_N 391      // ceil(N_NODES/256)
#define NB_E4 1172    // ceil(E_EDGES/1024)
#define NWARPS_G 6250 // N_NODES/16
#define NB_G 782      // ceil(6250/8)

// ---------------- scratch (static device globals; no allocation) ----------------
__device__ int   g_cnt[N_NODES];
__device__ int   g_rowptr[N_NODES + 1];
__device__ int   g_cursor[N_NODES];
__device__ int   g_csr_src[E_EDGES];
__device__ int   g_part[NB_N];
__device__ float g_Y[(size_t)N_NODES * DIM];
__device__ float g_Z[(size_t)N_NODES * DIM];
__device__ float g_H[(size_t)N_NODES * DIM];
// packed B fragments: [pair][ (nt*8+ks)*128 + lane*4 + {hi0,hi1,lo0,lo1} ]
__device__ float g_Bpack[2][16 * 8 * 32 * 4];

// ---------------- tf32 helpers ----------------
__device__ __forceinline__ unsigned cvt_tf32(float x) {
    unsigned r;
    asm("cvt.rna.tf32.f32 %0, %1;" : "=r"(r) : "f"(x));
    return r;
}
__device__ __forceinline__ void mma_tf32(float* c, const unsigned* a, unsigned b0, unsigned b1) {
    asm("mma.sync.aligned.m16n8k8.row.col.f32.tf32.tf32.f32 "
        "{%0,%1,%2,%3}, {%4,%5,%6,%7}, {%8,%9}, {%0,%1,%2,%3};"
        : "+f"(c[0]), "+f"(c[1]), "+f"(c[2]), "+f"(c[3])
        : "r"(a[0]), "r"(a[1]), "r"(a[2]), "r"(a[3]), "r"(b0), "r"(b1));
}

// ---------------- f32x2 helpers (head kernel) ----------------
__device__ __forceinline__ unsigned long long ffma2(unsigned long long a,
                                                    unsigned long long b,
                                                    unsigned long long c) {
    unsigned long long d;
    asm("fma.rn.f32x2 %0, %1, %2, %3;" : "=l"(d) : "l"(a), "l"(b), "l"(c));
    return d;
}
__device__ __forceinline__ unsigned long long dup2(float x) {
    unsigned long long d;
    unsigned u = __float_as_uint(x);
    asm("mov.b64 %0, {%1, %1};" : "=l"(d) : "r"(u));
    return d;
}
__device__ __forceinline__ float lo32(unsigned long long v) {
    return __uint_as_float((unsigned)(v & 0xffffffffull));
}
__device__ __forceinline__ float hi32(unsigned long long v) {
    return __uint_as_float((unsigned)(v >> 32));
}

// ---------------- prepack W fragments (hi/lo tf32), both layers ----------------
__global__ __launch_bounds__(256) void k_prepack(const float* __restrict__ Wl1,
                                                 const float* __restrict__ Wr1,
                                                 const float* __restrict__ Wl2,
                                                 const float* __restrict__ Wr2) {
    int pair = blockIdx.x;
    const float* Wl = pair ? Wl2 : Wl1;
    const float* Wr = pair ? Wr2 : Wr1;
    int t = threadIdx.x;
    for (int idx = t; idx < 4096; idx += 256) {   // 128 tiles * 32 lanes
        int tile = idx >> 5, lane = idx & 31;
        int nt = tile >> 3, ks = tile & 7;
        int n = nt * 8 + (lane >> 2);
        int k = ks * 8 + (lane & 3);
        const float* W = (n < 64) ? Wl : Wr;
        int nn = n & 63;
        float w0 = W[nn * 64 + k];
        float w1 = W[nn * 64 + k + 4];
        unsigned h0 = cvt_tf32(w0), h1 = cvt_tf32(w1);
        unsigned l0 = cvt_tf32(w0 - __uint_as_float(h0));
        unsigned l1 = cvt_tf32(w1 - __uint_as_float(h1));
        float4 v = make_float4(__uint_as_float(h0), __uint_as_float(h1),
                               __uint_as_float(l0), __uint_as_float(l1));
        ((float4*)(g_Bpack[pair]))[idx] = v;
    }
}

// ---------------- tensor-core GEMM pair: [Y|Z] = X @ [Wl|Wr]^T, 3xTF32 ----------------
__global__ __launch_bounds__(256) void k_gemm_tc(const float* __restrict__ X,
                                                 const float* __restrict__ pack,
                                                 float* __restrict__ Y,
                                                 float* __restrict__ Z) {
    int w = (blockIdx.x * 256 + threadIdx.x) >> 5;
    int lane = threadIdx.x & 31;
    if (w >= NWARPS_G) return;

    int g = lane >> 2;
    int tg = lane & 3;
    int r0 = w * 16 + g;

    float c[16][4];
#pragma unroll
    for (int nt = 0; nt < 16; nt++) {
        c[nt][0] = 0.f; c[nt][1] = 0.f; c[nt][2] = 0.f; c[nt][3] = 0.f;
    }

    const float4* bp = (const float4*)pack;

#pragma unroll
    for (int ks = 0; ks < 8; ks++) {
        int k = ks * 8 + tg;
        float a00 = X[(size_t)r0 * 64 + k];
        float a10 = X[(size_t)(r0 + 8) * 64 + k];
        float a01 = X[(size_t)r0 * 64 + k + 4];
        float a11 = X[(size_t)(r0 + 8) * 64 + k + 4];

        unsigned ah[4], al[4];
        ah[0] = cvt_tf32(a00); al[0] = cvt_tf32(a00 - __uint_as_float(ah[0]));
        ah[1] = cvt_tf32(a10); al[1] = cvt_tf32(a10 - __uint_as_float(ah[1]));
        ah[2] = cvt_tf32(a01); al[2] = cvt_tf32(a01 - __uint_as_float(ah[2]));
        ah[3] = cvt_tf32(a11); al[3] = cvt_tf32(a11 - __uint_as_float(ah[3]));

#pragma unroll
        for (int nt = 0; nt < 16; nt++) {
            float4 b = bp[(nt * 8 + ks) * 32 + lane];
            unsigned bh0 = __float_as_uint(b.x), bh1 = __float_as_uint(b.y);
            unsigned bl0 = __float_as_uint(b.z), bl1 = __float_as_uint(b.w);
            mma_tf32(c[nt], ah, bh0, bh1);
            mma_tf32(c[nt], ah, bl0, bl1);
            mma_tf32(c[nt], al, bh0, bh1);
        }
    }

#pragma unroll
    for (int nt = 0; nt < 16; nt++) {
        int n0 = nt * 8 + 2 * tg;
        float* O = (nt < 8) ? Y : Z;
        int col = n0 & 63;
        ((float2*)(O + (size_t)r0 * 64 + col))[0] = make_float2(c[nt][0], c[nt][1]);
        ((float2*)(O + (size_t)(r0 + 8) * 64 + col))[0] = make_float2(c[nt][2], c[nt][3]);
    }
}

// ---------------- CSR build ----------------
__global__ void k_zero_cnt() {
    int i = blockIdx.x * blockDim.x + threadIdx.x;
    if (i * 4 < N_NODES) {
        int4 z = make_int4(0, 0, 0, 0);
        if (i * 4 + 3 < N_NODES) ((int4*)g_cnt)[i] = z;
        else for (int j = i * 4; j < N_NODES; j++) g_cnt[j] = 0;
    }
}

// ILP-4 histogram: 4 independent edges per thread
__global__ __launch_bounds__(256) void k_hist(const int* __restrict__ ei) {
    int base = blockIdx.x * 1024 + threadIdx.x;
    int d[4];
#pragma unroll
    for (int u = 0; u < 4; u++) {
        int e = base + u * 256;
        d[u] = (e < E_EDGES) ? ei[E_EDGES + e] : -1;
    }
#pragma unroll
    for (int u = 0; u < 4; u++)
        if ((unsigned)d[u] < N_NODES) atomicAdd(&g_cnt[d[u]], 1);
}

__global__ __launch_bounds__(256) void k_blocksum() {
    __shared__ int sc[256];
    int t = threadIdx.x;
    int i = blockIdx.x * 256 + t;
    int v = (i < N_NODES) ? g_cnt[i] : 0;
    sc[t] = v;
    __syncthreads();
    for (int off = 128; off > 0; off >>= 1) {
        if (t < off) sc[t] += sc[t + off];
        __syncthreads();
    }
    if (t == 0) g_part[blockIdx.x] = sc[0];
}

__global__ __launch_bounds__(256) void k_scatter2() {
    __shared__ int sc[256];
    __shared__ int sbase[8];
    int t = threadIdx.x;
    int b = blockIdx.x;

    int acc = 0;
    for (int i = t; i < b; i += 256) acc += g_part[i];
#pragma unroll
    for (int o = 16; o > 0; o >>= 1) acc += __shfl_down_sync(0xffffffffu, acc, o);
    if ((t & 31) == 0) sbase[t >> 5] = acc;

    int i = b * 256 + t;
    int v = (i < N_NODES) ? g_cnt[i] : 0;
    sc[t] = v;
    __syncthreads();

    int base = 0;
#pragma unroll
    for (int w = 0; w < 8; w++) base += sbase[w];

    for (int off = 1; off < 256; off <<= 1) {
        int u = (t >= off) ? sc[t - off] : 0;
        __syncthreads();
        sc[t] += u;
        __syncthreads();
    }
    if (i < N_NODES) {
        int pos = base + sc[t] - v;
        g_rowptr[i] = pos;
        g_cursor[i] = pos;
    }
    if (b == NB_N - 1 && t == 255) g_rowptr[N_NODES] = base + sc[255];
}

// ILP-4 fill: 4 independent edges per thread
__global__ __launch_bounds__(256) void k_fill(const int* __restrict__ ei) {
    int base = blockIdx.x * 1024 + threadIdx.x;
    int s[4], d[4];
#pragma unroll
    for (int u = 0; u < 4; u++) {
        int e = base + u * 256;
        if (e < E_EDGES) { s[u] = ei[e]; d[u] = ei[E_EDGES + e]; }
        else { s[u] = -1; d[u] = -1; }
    }
    int pos[4];
#pragma unroll
    for (int u = 0; u < 4; u++)
        pos[u] = ((unsigned)d[u] < N_NODES && (unsigned)s[u] < N_NODES)
                     ? atomicAdd(&g_cursor[d[u]], 1) : -1;
#pragma unroll
    for (int u = 0; u < 4; u++)
        if (pos[u] >= 0) g_csr_src[pos[u]] = s[u];
}

// ---------------- warp-per-node: H = relu(BN(sum(Y[src])/max(deg,1) + bl + Z)) ----------------
__global__ __launch_bounds__(256) void k_agg(const float* __restrict__ Y,
                                             const float* __restrict__ Z,
                                             const float* __restrict__ bl,
                                             const float* __restrict__ gam,
                                             const float* __restrict__ bet,
                                             const float* __restrict__ mu,
                                             const float* __restrict__ var,
                                             float* __restrict__ H) {
    int warp = (blockIdx.x * blockDim.x + threadIdx.x) >> 5;
    int lane = threadIdx.x & 31;
    if (warp >= N_NODES) return;

    int r0 = g_rowptr[warp];
    int r1 = g_rowptr[warp + 1];

    const float2* Y2 = (const float2*)Y;
    float ax = 0.f, ay = 0.f;

    int e = r0;
    for (; e + 4 <= r1; e += 4) {
        int s0 = g_csr_src[e];
        int s1 = g_csr_src[e + 1];
        int s2 = g_csr_src[e + 2];
        int s3 = g_csr_src[e + 3];
        float2 v0 = Y2[(size_t)s0 * 32 + lane];
        float2 v1 = Y2[(size_t)s1 * 32 + lane];
        float2 v2 = Y2[(size_t)s2 * 32 + lane];
        float2 v3 = Y2[(size_t)s3 * 32 + lane];
        ax += (v0.x + v1.x) + (v2.x + v3.x);
        ay += (v0.y + v1.y) + (v2.y + v3.y);
    }
    if (e + 2 <= r1) {
        int s0 = g_csr_src[e];
        int s1 = g_csr_src[e + 1];
        float2 v0 = Y2[(size_t)s0 * 32 + lane];
        float2 v1 = Y2[(size_t)s1 * 32 + lane];
        ax += v0.x + v1.x;
        ay += v0.y + v1.y;
        e += 2;
    }
    if (e < r1) {
        float2 v = Y2[(size_t)g_csr_src[e] * 32 + lane];
        ax += v.x;
        ay += v.y;
    }

    int deg = r1 - r0;
    float inv = 1.f / (float)(deg > 0 ? deg : 1);

    int j0 = 2 * lane, j1 = 2 * lane + 1;
    float2 z = ((const float2*)Z)[(size_t)warp * 32 + lane];
    float h0 = ax * inv + bl[j0] + z.x;
    float h1 = ay * inv + bl[j1] + z.y;
    float s0 = gam[j0] * rsqrtf(var[j0] + EPS_BN);
    float s1 = gam[j1] * rsqrtf(var[j1] + EPS_BN);
    h0 = fmaxf((h0 - mu[j0]) * s0 + bet[j0], 0.f);
    h1 = fmaxf((h1 - mu[j1]) * s1 + bet[j1], 0.f);
    ((float2*)H)[(size_t)warp * 32 + lane] = make_float2(h0, h1);
}

// ---------------- MLP head ----------------
__global__ __launch_bounds__(256) void k_head(const float* __restrict__ Hh,
                                              const float* __restrict__ mW1,
                                              const float* __restrict__ mb1,
                                              const float* __restrict__ mW2,
                                              const float* __restrict__ mb2,
                                              float* __restrict__ out) {
    __shared__ float2 sWp[64 * 16];
    __shared__ float sb1[32];
    __shared__ float sw2[32];
    __shared__ float sb2;
    int tid = threadIdx.x;
    for (int i = tid; i < 1024; i += 256) {
        int p = i >> 6, k = i & 63;
        sWp[k * 16 + p] = make_float2(mW1[(2 * p) * 64 + k], mW1[(2 * p + 1) * 64 + k]);
    }
    if (tid < 32) { sb1[tid] = mb1[tid]; sw2[tid] = mW2[tid]; }
    if (tid == 0) sb2 = mb2[0];
    __syncthreads();

    int n = blockIdx.x * 256 + tid;
    if (n >= N_NODES) return;

    unsigned long long acc[16];
#pragma unroll
    for (int p = 0; p < 16; p++) acc[p] = 0ull;

    const float4* xr = (const float4*)(Hh + (size_t)n * DIM);
#pragma unroll 4
    for (int kk = 0; kk < 16; kk++) {
        float4 x4 = xr[kk];
        float xs[4] = {x4.x, x4.y, x4.z, x4.w};
#pragma unroll
        for (int t = 0; t < 4; t++) {
            int k = kk * 4 + t;
            unsigned long long x2 = dup2(xs[t]);
            const ulonglong2* wrow = (const ulonglong2*)(sWp + k * 16);
#pragma unroll
            for (int q = 0; q < 8; q++) {
                ulonglong2 w2 = wrow[q];
                acc[2 * q]     = ffma2(x2, w2.x, acc[2 * q]);
                acc[2 * q + 1] = ffma2(x2, w2.y, acc[2 * q + 1]);
            }
        }
    }
    float o = sb2;
#pragma unroll
    for (int p = 0; p < 16; p++) {
        o += fmaxf(lo32(acc[p]) + sb1[2 * p], 0.f) * sw2[2 * p];
        o += fmaxf(hi32(acc[p]) + sb1[2 * p + 1], 0.f) * sw2[2 * p + 1];
    }
    out[n] = 1.f / (1.f + __expf(-o));
}

// ---------------- launch ----------------
extern "C" void kernel_launch(void* const* d_in, const int* in_sizes, int n_in,
                              void* d_out, int out_size) {
    const float* x    = (const float*)d_in[0];
    const int*   ei   = (const int*)d_in[1];
    const float* Wl1  = (const float*)d_in[2];
    const float* bl1  = (const float*)d_in[3];
    const float* Wr1  = (const float*)d_in[4];
    const float* g1   = (const float*)d_in[5];
    const float* be1  = (const float*)d_in[6];
    const float* m1   = (const float*)d_in[7];
    const float* v1   = (const float*)d_in[8];
    const float* Wl2  = (const float*)d_in[9];
    const float* bl2  = (const float*)d_in[10];
    const float* Wr2  = (const float*)d_in[11];
    const float* g2   = (const float*)d_in[12];
    const float* be2  = (const float*)d_in[13];
    const float* m2   = (const float*)d_in[14];
    const float* v2   = (const float*)d_in[15];
    const float* mW1  = (const float*)d_in[16];
    const float* mb1  = (const float*)d_in[17];
    const float* mW2  = (const float*)d_in[18];
    const float* mb2  = (const float*)d_in[19];
    float* out = (float*)d_out;

    float* Y; cudaGetSymbolAddress((void**)&Y, g_Y);
    float* Z; cudaGetSymbolAddress((void**)&Z, g_Z);
    float* H; cudaGetSymbolAddress((void**)&H, g_H);
    float* Bp; cudaGetSymbolAddress((void**)&Bp, g_Bpack);

    const int NB_W = (N_NODES * 32 + 255) / 256;   // 12500

    static cudaStream_t sb = nullptr;
    static cudaEvent_t evFork = nullptr, evJoin = nullptr;
    if (!sb) {
        cudaStreamCreateWithFlags(&sb, cudaStreamNonBlocking);
        cudaEventCreateWithFlags(&evFork, cudaEventDisableTiming);
        cudaEventCreateWithFlags(&evJoin, cudaEventDisableTiming);
    }

    // fork: CSR chain on side stream, concurrent with prepack + layer-1 GEMM
    cudaEventRecord(evFork, 0);
    cudaStreamWaitEvent(sb, evFork, 0);
    k_zero_cnt<<<(N_NODES / 4 + 255) / 256, 256, 0, sb>>>();
    k_hist<<<NB_E4, 256, 0, sb>>>(ei);
    k_blocksum<<<NB_N, 256, 0, sb>>>();
    k_scatter2<<<NB_N, 256, 0, sb>>>();
    k_fill<<<NB_E4, 256, 0, sb>>>(ei);
    cudaEventRecord(evJoin, sb);

    // main stream
    k_prepack<<<2, 256>>>(Wl1, Wr1, Wl2, Wr2);
    k_gemm_tc<<<NB_G, 256>>>(x, Bp, Y, Z);               // layer-1 pair
    cudaStreamWaitEvent(0, evJoin, 0);

    k_agg<<<NB_W, 256>>>(Y, Z, bl1, g1, be1, m1, v1, H);

    k_gemm_tc<<<NB_G, 256>>>(H, Bp + 16384, Y, Z);       // layer-2 pair
    k_agg<<<NB_W, 256>>>(Y, Z, bl2, g2, be2, m2, v2, H);

    k_head<<<NB_N, 256>>>(H, mW1, mb1, mW2, mb2, out);
}

// round 9
// speedup vs baseline: 1.3731x; 1.0300x over previous
#include <cuda_runtime.h>

#define N_NODES 100000
#define E_EDGES 1200000
#define DIM 64
#define EPS_BN 1e-5f
#define NB_N 391      // ceil(N_NODES/256)
#define NB_E4 1172    // ceil(E_EDGES/1024)
#define NWARPS_G 6250 // N_NODES/16
#define NB_G 782      // ceil(6250/8)
#define NB_T 6250     // node-tile blocks (16 nodes each)
#define SH_STRIDE 66  // padded row stride (floats) for h staging

// ---------------- scratch (static device globals; no allocation) ----------------
__device__ int   g_cnt[N_NODES];
__device__ int   g_rowptr[N_NODES + 1];
__device__ int   g_cursor[N_NODES];
__device__ int   g_csr_src[E_EDGES];
__device__ int   g_part[NB_N];
__device__ float g_Y[(size_t)N_NODES * DIM];
__device__ float g_Z[(size_t)N_NODES * DIM];
__device__ float g_Y2[(size_t)N_NODES * DIM];
__device__ float g_Z2[(size_t)N_NODES * DIM];
// packed B fragments: [pair][ (nt*8+ks)*128 + lane*4 + {hi0,hi1,lo0,lo1} ]
__device__ float g_Bpack[2][16 * 8 * 32 * 4];
__device__ float g_BpackH[4 * 8 * 32 * 4];   // head W1 (32x64)

// ---------------- tf32 helpers ----------------
__device__ __forceinline__ unsigned cvt_tf32(float x) {
    unsigned r;
    asm("cvt.rna.tf32.f32 %0, %1;" : "=r"(r) : "f"(x));
    return r;
}
__device__ __forceinline__ void mma_tf32(float* c, const unsigned* a, unsigned b0, unsigned b1) {
    asm("mma.sync.aligned.m16n8k8.row.col.f32.tf32.tf32.f32 "
        "{%0,%1,%2,%3}, {%4,%5,%6,%7}, {%8,%9}, {%0,%1,%2,%3};"
        : "+f"(c[0]), "+f"(c[1]), "+f"(c[2]), "+f"(c[3])
        : "r"(a[0]), "r"(a[1]), "r"(a[2]), "r"(a[3]), "r"(b0), "r"(b1));
}

// ---------------- prepack W fragments (hi/lo tf32): 2 layer pairs + head ----------------
__global__ __launch_bounds__(256) void k_prepack(const float* __restrict__ Wl1,
                                                 const float* __restrict__ Wr1,
                                                 const float* __restrict__ Wl2,
                                                 const float* __restrict__ Wr2,
                                                 const float* __restrict__ mW1) {
    int b = blockIdx.x;
    int t = threadIdx.x;
    if (b < 2) {
        const float* Wl = b ? Wl2 : Wl1;
        const float* Wr = b ? Wr2 : Wr1;
        for (int idx = t; idx < 4096; idx += 256) {
            int tile = idx >> 5, lane = idx & 31;
            int nt = tile >> 3, ks = tile & 7;
            int n = nt * 8 + (lane >> 2);
            int k = ks * 8 + (lane & 3);
            const float* W = (n < 64) ? Wl : Wr;
            int nn = n & 63;
            float w0 = W[nn * 64 + k];
            float w1 = W[nn * 64 + k + 4];
            unsigned h0 = cvt_tf32(w0), h1 = cvt_tf32(w1);
            unsigned l0 = cvt_tf32(w0 - __uint_as_float(h0));
            unsigned l1 = cvt_tf32(w1 - __uint_as_float(h1));
            ((float4*)(g_Bpack[b]))[idx] =
                make_float4(__uint_as_float(h0), __uint_as_float(h1),
                            __uint_as_float(l0), __uint_as_float(l1));
        }
    } else {
        for (int idx = t; idx < 1024; idx += 256) {   // 32 tiles (4 nt x 8 ks)
            int tile = idx >> 5, lane = idx & 31;
            int nt = tile >> 3, ks = tile & 7;
            int n = nt * 8 + (lane >> 2);             // 0..31 rows of mW1
            int k = ks * 8 + (lane & 3);
            float w0 = mW1[n * 64 + k];
            float w1 = mW1[n * 64 + k + 4];
            unsigned h0 = cvt_tf32(w0), h1 = cvt_tf32(w1);
            unsigned l0 = cvt_tf32(w0 - __uint_as_float(h0));
            unsigned l1 = cvt_tf32(w1 - __uint_as_float(h1));
            ((float4*)g_BpackH)[idx] =
                make_float4(__uint_as_float(h0), __uint_as_float(h1),
                            __uint_as_float(l0), __uint_as_float(l1));
        }
    }
}

// ---------------- layer-1 TC GEMM pair: [Y|Z] = X @ [Wl|Wr]^T, 3xTF32 ----------------
__global__ __launch_bounds__(256) void k_gemm_tc(const float* __restrict__ X,
                                                 const float* __restrict__ pack,
                                                 float* __restrict__ Y,
                                                 float* __restrict__ Z) {
    int w = (blockIdx.x * 256 + threadIdx.x) >> 5;
    int lane = threadIdx.x & 31;
    if (w >= NWARPS_G) return;

    int g = lane >> 2;
    int tg = lane & 3;
    int r0 = w * 16 + g;

    float c[16][4];
#pragma unroll
    for (int nt = 0; nt < 16; nt++) {
        c[nt][0] = 0.f; c[nt][1] = 0.f; c[nt][2] = 0.f; c[nt][3] = 0.f;
    }

    const float4* bp = (const float4*)pack;

#pragma unroll
    for (int ks = 0; ks < 8; ks++) {
        int k = ks * 8 + tg;
        float a00 = X[(size_t)r0 * 64 + k];
        float a10 = X[(size_t)(r0 + 8) * 64 + k];
        float a01 = X[(size_t)r0 * 64 + k + 4];
        float a11 = X[(size_t)(r0 + 8) * 64 + k + 4];

        unsigned ah[4], al[4];
        ah[0] = cvt_tf32(a00); al[0] = cvt_tf32(a00 - __uint_as_float(ah[0]));
        ah[1] = cvt_tf32(a10); al[1] = cvt_tf32(a10 - __uint_as_float(ah[1]));
        ah[2] = cvt_tf32(a01); al[2] = cvt_tf32(a01 - __uint_as_float(ah[2]));
        ah[3] = cvt_tf32(a11); al[3] = cvt_tf32(a11 - __uint_as_float(ah[3]));

#pragma unroll
        for (int nt = 0; nt < 16; nt++) {
            float4 b = bp[(nt * 8 + ks) * 32 + lane];
            mma_tf32(c[nt], ah, __float_as_uint(b.x), __float_as_uint(b.y));
            mma_tf32(c[nt], ah, __float_as_uint(b.z), __float_as_uint(b.w));
            mma_tf32(c[nt], al, __float_as_uint(b.x), __float_as_uint(b.y));
        }
    }

#pragma unroll
    for (int nt = 0; nt < 16; nt++) {
        int n0 = nt * 8 + 2 * tg;
        float* O = (nt < 8) ? Y : Z;
        int col = n0 & 63;
        ((float2*)(O + (size_t)r0 * 64 + col))[0] = make_float2(c[nt][0], c[nt][1]);
        ((float2*)(O + (size_t)(r0 + 8) * 64 + col))[0] = make_float2(c[nt][2], c[nt][3]);
    }
}

// ---------------- CSR build ----------------
__global__ void k_zero_cnt() {
    int i = blockIdx.x * blockDim.x + threadIdx.x;
    if (i * 4 < N_NODES) {
        int4 z = make_int4(0, 0, 0, 0);
        if (i * 4 + 3 < N_NODES) ((int4*)g_cnt)[i] = z;
        else for (int j = i * 4; j < N_NODES; j++) g_cnt[j] = 0;
    }
}

__global__ __launch_bounds__(256) void k_hist(const int* __restrict__ ei) {
    int base = blockIdx.x * 1024 + threadIdx.x;
    int d[4];
#pragma unroll
    for (int u = 0; u < 4; u++) {
        int e = base + u * 256;
        d[u] = (e < E_EDGES) ? ei[E_EDGES + e] : -1;
    }
#pragma unroll
    for (int u = 0; u < 4; u++)
        if ((unsigned)d[u] < N_NODES) atomicAdd(&g_cnt[d[u]], 1);
}

__global__ __launch_bounds__(256) void k_blocksum() {
    __shared__ int sc[256];
    int t = threadIdx.x;
    int i = blockIdx.x * 256 + t;
    int v = (i < N_NODES) ? g_cnt[i] : 0;
    sc[t] = v;
    __syncthreads();
    for (int off = 128; off > 0; off >>= 1) {
        if (t < off) sc[t] += sc[t + off];
        __syncthreads();
    }
    if (t == 0) g_part[blockIdx.x] = sc[0];
}

__global__ __launch_bounds__(256) void k_scatter2() {
    __shared__ int sc[256];
    __shared__ int sbase[8];
    int t = threadIdx.x;
    int b = blockIdx.x;

    int acc = 0;
    for (int i = t; i < b; i += 256) acc += g_part[i];
#pragma unroll
    for (int o = 16; o > 0; o >>= 1) acc += __shfl_down_sync(0xffffffffu, acc, o);
    if ((t & 31) == 0) sbase[t >> 5] = acc;

    int i = b * 256 + t;
    int v = (i < N_NODES) ? g_cnt[i] : 0;
    sc[t] = v;
    __syncthreads();

    int base = 0;
#pragma unroll
    for (int w = 0; w < 8; w++) base += sbase[w];

    for (int off = 1; off < 256; off <<= 1) {
        int u = (t >= off) ? sc[t - off] : 0;
        __syncthreads();
        sc[t] += u;
        __syncthreads();
    }
    if (i < N_NODES) {
        int pos = base + sc[t] - v;
        g_rowptr[i] = pos;
        g_cursor[i] = pos;
    }
    if (b == NB_N - 1 && t == 255) g_rowptr[N_NODES] = base + sc[255];
}

__global__ __launch_bounds__(256) void k_fill(const int* __restrict__ ei) {
    int base = blockIdx.x * 1024 + threadIdx.x;
    int s[4], d[4];
#pragma unroll
    for (int u = 0; u < 4; u++) {
        int e = base + u * 256;
        if (e < E_EDGES) { s[u] = ei[e]; d[u] = ei[E_EDGES + e]; }
        else { s[u] = -1; d[u] = -1; }
    }
    int pos[4];
#pragma unroll
    for (int u = 0; u < 4; u++)
        pos[u] = ((unsigned)d[u] < N_NODES && (unsigned)s[u] < N_NODES)
                     ? atomicAdd(&g_cursor[d[u]], 1) : -1;
#pragma unroll
    for (int u = 0; u < 4; u++)
        if (pos[u] >= 0) g_csr_src[pos[u]] = s[u];
}

// ---------------- gather body: mean-aggregate Y rows of node 'warp' ----------------
__device__ __forceinline__ void gather_body(const float* __restrict__ Y, int warp, int lane,
                                            float& ax, float& ay, float& inv) {
    int r0 = g_rowptr[warp];
    int r1 = g_rowptr[warp + 1];

    const float2* Y2 = (const float2*)Y;
    ax = 0.f; ay = 0.f;

    int e = r0;
    for (; e + 4 <= r1; e += 4) {
        int s0 = g_csr_src[e];
        int s1 = g_csr_src[e + 1];
        int s2 = g_csr_src[e + 2];
        int s3 = g_csr_src[e + 3];
        float2 v0 = Y2[(size_t)s0 * 32 + lane];
        float2 v1 = Y2[(size_t)s1 * 32 + lane];
        float2 v2 = Y2[(size_t)s2 * 32 + lane];
        float2 v3 = Y2[(size_t)s3 * 32 + lane];
        ax += (v0.x + v1.x) + (v2.x + v3.x);
        ay += (v0.y + v1.y) + (v2.y + v3.y);
    }
    if (e + 2 <= r1) {
        int s0 = g_csr_src[e];
        int s1 = g_csr_src[e + 1];
        float2 v0 = Y2[(size_t)s0 * 32 + lane];
        float2 v1 = Y2[(size_t)s1 * 32 + lane];
        ax += v0.x + v1.x;
        ay += v0.y + v1.y;
        e += 2;
    }
    if (e < r1) {
        float2 v = Y2[(size_t)g_csr_src[e] * 32 + lane];
        ax += v.x;
        ay += v.y;
    }
    int deg = r1 - r0;
    inv = 1.f / (float)(deg > 0 ? deg : 1);
}

// ---------------- BN+ReLU epilogue for lane's feature pair ----------------
__device__ __forceinline__ float2 bn_relu(float ax, float ay, float inv, int lane,
                                          const float* __restrict__ Z, int node,
                                          const float* __restrict__ bl,
                                          const float* __restrict__ gam,
                                          const float* __restrict__ bet,
                                          const float* __restrict__ mu,
                                          const float* __restrict__ var) {
    int j0 = 2 * lane, j1 = 2 * lane + 1;
    float2 z = ((const float2*)Z)[(size_t)node * 32 + lane];
    float h0 = ax * inv + bl[j0] + z.x;
    float h1 = ay * inv + bl[j1] + z.y;
    float s0 = gam[j0] * rsqrtf(var[j0] + EPS_BN);
    float s1 = gam[j1] * rsqrtf(var[j1] + EPS_BN);
    h0 = fmaxf((h0 - mu[j0]) * s0 + bet[j0], 0.f);
    h1 = fmaxf((h1 - mu[j1]) * s1 + bet[j1], 0.f);
    return make_float2(h0, h1);
}

// ---------------- fused: agg1 (BN1+ReLU) + layer-2 GEMM pair -> Y2, Z2 ----------------
__global__ __launch_bounds__(512) void k_agg1_gemm2(const float* __restrict__ Y,
                                                    const float* __restrict__ Z,
                                                    const float* __restrict__ bl,
                                                    const float* __restrict__ gam,
                                                    const float* __restrict__ bet,
                                                    const float* __restrict__ mu,
                                                    const float* __restrict__ var,
                                                    const float* __restrict__ pack,
                                                    float* __restrict__ Yo,
                                                    float* __restrict__ Zo) {
    __shared__ float sH[16 * SH_STRIDE];
    int tid = threadIdx.x;
    int wid = tid >> 5;
    int lane = tid & 31;
    int base = blockIdx.x * 16;
    int node = base + wid;

    float ax, ay, inv;
    gather_body(Y, node, lane, ax, ay, inv);
    float2 h = bn_relu(ax, ay, inv, lane, Z, node, bl, gam, bet, mu, var);
    ((float2*)(sH + wid * SH_STRIDE))[lane] = h;
    __syncthreads();

    // MMA phase: warp wid computes n-tile nt=wid over the 16-row tile
    int nt = wid;
    int g = lane >> 2;
    int tg = lane & 3;

    float c[4] = {0.f, 0.f, 0.f, 0.f};
    const float4* bp = (const float4*)pack;

#pragma unroll
    for (int ks = 0; ks < 8; ks++) {
        int k = ks * 8 + tg;
        float a00 = sH[g * SH_STRIDE + k];
        float a10 = sH[(g + 8) * SH_STRIDE + k];
        float a01 = sH[g * SH_STRIDE + k + 4];
        float a11 = sH[(g + 8) * SH_STRIDE + k + 4];

        unsigned ah[4], al[4];
        ah[0] = cvt_tf32(a00); al[0] = cvt_tf32(a00 - __uint_as_float(ah[0]));
        ah[1] = cvt_tf32(a10); al[1] = cvt_tf32(a10 - __uint_as_float(ah[1]));
        ah[2] = cvt_tf32(a01); al[2] = cvt_tf32(a01 - __uint_as_float(ah[2]));
        ah[3] = cvt_tf32(a11); al[3] = cvt_tf32(a11 - __uint_as_float(ah[3]));

        float4 b = bp[(nt * 8 + ks) * 32 + lane];
        mma_tf32(c, ah, __float_as_uint(b.x), __float_as_uint(b.y));
        mma_tf32(c, ah, __float_as_uint(b.z), __float_as_uint(b.w));
        mma_tf32(c, al, __float_as_uint(b.x), __float_as_uint(b.y));
    }

    float* O = (nt < 8) ? Yo : Zo;
    int col = (nt * 8 + 2 * tg) & 63;
    ((float2*)(O + (size_t)(base + g) * 64 + col))[0] = make_float2(c[0], c[1]);
    ((float2*)(O + (size_t)(base + g + 8) * 64 + col))[0] = make_float2(c[2], c[3]);
}

// ---------------- fused: agg2 (BN2+ReLU) + MLP head -> out ----------------
__global__ __launch_bounds__(512) void k_agg2_head(const float* __restrict__ Y,
                                                   const float* __restrict__ Z,
                                                   const float* __restrict__ bl,
                                                   const float* __restrict__ gam,
                                                   const float* __restrict__ bet,
                                                   const float* __restrict__ mu,
                                                   const float* __restrict__ var,
                                                   const float* __restrict__ packH,
                                                   const float* __restrict__ mb1,
                                                   const float* __restrict__ mW2,
                                                   const float* __restrict__ mb2,
                                                   float* __restrict__ out) {
    __shared__ float sH[16 * SH_STRIDE];
    __shared__ float spart[64];
    int tid = threadIdx.x;
    int wid = tid >> 5;
    int lane = tid & 31;
    int base = blockIdx.x * 16;
    int node = base + wid;

    float ax, ay, inv;
    gather_body(Y, node, lane, ax, ay, inv);
    float2 h = bn_relu(ax, ay, inv, lane, Z, node, bl, gam, bet, mu, var);
    ((float2*)(sH + wid * SH_STRIDE))[lane] = h;
    __syncthreads();

    if (wid < 4) {
        int nt = wid;
        int g = lane >> 2;
        int tg = lane & 3;

        float c[4] = {0.f, 0.f, 0.f, 0.f};
        const float4* bp = (const float4*)packH;

#pragma unroll
        for (int ks = 0; ks < 8; ks++) {
            int k = ks * 8 + tg;
            float a00 = sH[g * SH_STRIDE + k];
            float a10 = sH[(g + 8) * SH_STRIDE + k];
            float a01 = sH[g * SH_STRIDE + k + 4];
            float a11 = sH[(g + 8) * SH_STRIDE + k + 4];

            unsigned ah[4], al[4];
            ah[0] = cvt_tf32(a00); al[0] = cvt_tf32(a00 - __uint_as_float(ah[0]));
            ah[1] = cvt_tf32(a10); al[1] = cvt_tf32(a10 - __uint_as_float(ah[1]));
            ah[2] = cvt_tf32(a01); al[2] = cvt_tf32(a01 - __uint_as_float(ah[2]));
            ah[3] = cvt_tf32(a11); al[3] = cvt_tf32(a11 - __uint_as_float(ah[3]));

            float4 b = bp[(nt * 8 + ks) * 32 + lane];
            mma_tf32(c, ah, __float_as_uint(b.x), __float_as_uint(b.y));
            mma_tf32(c, ah, __float_as_uint(b.z), __float_as_uint(b.w));
            mma_tf32(c, al, __float_as_uint(b.x), __float_as_uint(b.y));
        }

        int j = nt * 8 + 2 * tg;
        float b1a = mb1[j], b1b = mb1[j + 1];
        float w2a = mW2[j], w2b = mW2[j + 1];
        float v0 = fmaxf(c[0] + b1a, 0.f) * w2a + fmaxf(c[1] + b1b, 0.f) * w2b;
        float v1 = fmaxf(c[2] + b1a, 0.f) * w2a + fmaxf(c[3] + b1b, 0.f) * w2b;
        v0 += __shfl_xor_sync(0xffffffffu, v0, 1);
        v0 += __shfl_xor_sync(0xffffffffu, v0, 2);
        v1 += __shfl_xor_sync(0xffffffffu, v1, 1);
        v1 += __shfl_xor_sync(0xffffffffu, v1, 2);
        if (tg == 0) {
            spart[nt * 16 + g] = v0;
            spart[nt * 16 + g + 8] = v1;
        }
    }
    __syncthreads();

    if (tid < 16) {
        float s = spart[tid] + spart[16 + tid] + spart[32 + tid] + spart[48 + tid] + mb2[0];
        out[base + tid] = 1.f / (1.f + __expf(-s));
    }
}

// ---------------- launch ----------------
extern "C" void kernel_launch(void* const* d_in, const int* in_sizes, int n_in,
                              void* d_out, int out_size) {
    const float* x    = (const float*)d_in[0];
    const int*   ei   = (const int*)d_in[1];
    const float* Wl1  = (const float*)d_in[2];
    const float* bl1  = (const float*)d_in[3];
    const float* Wr1  = (const float*)d_in[4];
    const float* g1   = (const float*)d_in[5];
    const float* be1  = (const float*)d_in[6];
    const float* m1   = (const float*)d_in[7];
    const float* v1   = (const float*)d_in[8];
    const float* Wl2  = (const float*)d_in[9];
    const float* bl2  = (const float*)d_in[10];
    const float* Wr2  = (const float*)d_in[11];
    const float* g2   = (const float*)d_in[12];
    const float* be2  = (const float*)d_in[13];
    const float* m2   = (const float*)d_in[14];
    const float* v2   = (const float*)d_in[15];
    const float* mW1  = (const float*)d_in[16];
    const float* mb1  = (const float*)d_in[17];
    const float* mW2  = (const float*)d_in[18];
    const float* mb2  = (const float*)d_in[19];
    float* out = (float*)d_out;

    float* Y;  cudaGetSymbolAddress((void**)&Y, g_Y);
    float* Z;  cudaGetSymbolAddress((void**)&Z, g_Z);
    float* Y2; cudaGetSymbolAddress((void**)&Y2, g_Y2);
    float* Z2; cudaGetSymbolAddress((void**)&Z2, g_Z2);
    float* Bp; cudaGetSymbolAddress((void**)&Bp, g_Bpack);
    float* BpH; cudaGetSymbolAddress((void**)&BpH, g_BpackH);

    static cudaStream_t sb = nullptr;
    static cudaEvent_t evFork = nullptr, evJoin = nullptr;
    if (!sb) {
        cudaStreamCreateWithFlags(&sb, cudaStreamNonBlocking);
        cudaEventCreateWithFlags(&evFork, cudaEventDisableTiming);
        cudaEventCreateWithFlags(&evJoin, cudaEventDisableTiming);
    }

    // fork: CSR chain on side stream, concurrent with prepack + layer-1 GEMM
    cudaEventRecord(evFork, 0);
    cudaStreamWaitEvent(sb, evFork, 0);
    k_zero_cnt<<<(N_NODES / 4 + 255) / 256, 256, 0, sb>>>();
    k_hist<<<NB_E4, 256, 0, sb>>>(ei);
    k_blocksum<<<NB_N, 256, 0, sb>>>();
    k_scatter2<<<NB_N, 256, 0, sb>>>();
    k_fill<<<NB_E4, 256, 0, sb>>>(ei);
    cudaEventRecord(evJoin, sb);

    // main stream
    k_prepack<<<3, 256>>>(Wl1, Wr1, Wl2, Wr2, mW1);
    k_gemm_tc<<<NB_G, 256>>>(x, Bp, Y, Z);                 // layer-1 pair
    cudaStreamWaitEvent(0, evJoin, 0);

    // layer-1 aggregate fused with layer-2 GEMM pair
    k_agg1_gemm2<<<NB_T, 512>>>(Y, Z, bl1, g1, be1, m1, v1, Bp + 16384, Y2, Z2);
    // layer-2 aggregate fused with MLP head
    k_agg2_head<<<NB_T, 512>>>(Y2, Z2, bl2, g2, be2, m2, v2, BpH, mb1, mW2, mb2, out);
}